// round 1
// baseline (speedup 1.0000x reference)
#include <cuda_runtime.h>

#define POOLP 7
#define MAXROIS 4096
#define NCHAN 256

struct RoiParams {
    int   y0[8];
    int   y1[8];
    int   x0[8];
    int   x1[8];
    float ly[8];
    float lx[8];
    int   level;   // 2..5
    int   hw;      // H*W of selected level
    int   w;       // W of selected level
    unsigned vmask; // bits [0..6] = valid_y, bits [8..14] = valid_x
};
// 208 bytes = 52 words

__device__ RoiParams g_prm[MAXROIS];

__global__ void roi_setup(const float* __restrict__ rois, int nrois) {
    int n = blockIdx.x * blockDim.x + threadIdx.x;
    if (n >= nrois) return;

    float rx1 = rois[4 * n + 0];
    float ry1 = rois[4 * n + 1];
    float rx2 = rois[4 * n + 2];
    float ry2 = rois[4 * n + 3];

    // level = clip(round(log2(sqrt(area)/224)) + 4, 2, 5)
    float area = (ry2 - ry1) * (rx2 - rx1);
    float lvlf = log2f(sqrtf(fmaxf(area, 0.0f)) / 224.0f);
    int level = (int)rintf(lvlf) + 4;     // rintf = round-half-even, matches jnp.round
    level = min(5, max(2, level));

    int H = 1024 >> level;                // 256,128,64,32 for levels 2..5
    float scale = (float)(H - 1);

    // normalized (y1,x1,y2,x2) = rois[:,[1,0,3,2]] / 1024
    float ny1 = ry1 * (1.0f / 1024.0f);
    float nx1 = rx1 * (1.0f / 1024.0f);
    float ny2 = ry2 * (1.0f / 1024.0f);
    float nx2 = rx2 * (1.0f / 1024.0f);

    float dy = __fsub_rn(ny2, ny1);
    float dx = __fsub_rn(nx2, nx1);

    RoiParams p;
    unsigned vm = 0u;

    #pragma unroll
    for (int i = 0; i < POOLP; i++) {
        float t = (float)i / 6.0f;  // arange(P)/(P-1), correctly-rounded division

        // ys = (ny1 + t*dy) * (H-1) — explicit rn ops, no FMA contraction
        float ys = __fmul_rn(__fadd_rn(ny1, __fmul_rn(t, dy)), scale);
        float xs = __fmul_rn(__fadd_rn(nx1, __fmul_rn(t, dx)), scale);

        bool vy = (ys >= 0.0f) && (ys <= scale);
        bool vx = (xs >= 0.0f) && (xs <= scale);
        if (vy) vm |= (1u << i);
        if (vx) vm |= (1u << (8 + i));

        float ysc = fminf(fmaxf(ys, 0.0f), scale);
        float xsc = fminf(fmaxf(xs, 0.0f), scale);

        int y0 = (int)floorf(ysc);
        int x0 = (int)floorf(xsc);
        int y1i = min(y0 + 1, H - 1);
        int x1i = min(x0 + 1, H - 1);

        p.y0[i] = y0;
        p.y1[i] = y1i;
        p.x0[i] = x0;
        p.x1[i] = x1i;
        p.ly[i] = __fsub_rn(ysc, (float)y0);
        p.lx[i] = __fsub_rn(xsc, (float)x0);
    }
    p.y0[7] = p.y1[7] = p.x0[7] = p.x1[7] = 0;
    p.ly[7] = p.lx[7] = 0.0f;
    p.level = level;
    p.hw = H * H;
    p.w = H;
    p.vmask = vm;

    g_prm[n] = p;
}

__global__ __launch_bounds__(512) void roi_pool(
    const float* __restrict__ p2, const float* __restrict__ p3,
    const float* __restrict__ p4, const float* __restrict__ p5,
    float* __restrict__ out)
{
    __shared__ RoiParams sp;
    int n = blockIdx.x;

    if (threadIdx.x < sizeof(RoiParams) / 4)
        ((int*)&sp)[threadIdx.x] = ((const int*)&g_prm[n])[threadIdx.x];
    __syncthreads();

    // image 0 of the selected level (reference uses feature_maps[i][0] for ALL rois)
    const float* fm = (sp.level == 2) ? p2
                    : (sp.level == 3) ? p3
                    : (sp.level == 4) ? p4 : p5;

    int pt   = threadIdx.x & 63;   // sample point within 7x7 (49 active)
    int cofs = threadIdx.x >> 6;   // channel group 0..7
    if (pt >= 49) return;

    int py = pt / 7;
    int px = pt - py * 7;

    int w    = sp.w;
    int hw   = sp.hw;
    int rowA = sp.y0[py] * w;
    int rowB = sp.y1[py] * w;
    int xa   = sp.x0[px];
    int xb   = sp.x1[px];
    float ly = sp.ly[py];
    float lx = sp.lx[px];
    float m  = (((sp.vmask >> py) & 1u) & ((sp.vmask >> (8 + px)) & 1u)) ? 1.0f : 0.0f;

    int obase = n * (NCHAN * 49) + pt;

    #pragma unroll 4
    for (int c = cofs; c < NCHAN; c += 8) {
        const float* fc = fm + c * hw;
        float tl = __ldg(fc + rowA + xa);
        float tr = __ldg(fc + rowA + xb);
        float bl = __ldg(fc + rowB + xa);
        float br = __ldg(fc + rowB + xb);
        float top = fmaf(tr - tl, lx, tl);
        float bot = fmaf(br - bl, lx, bl);
        float v   = fmaf(bot - top, ly, top) * m;
        out[obase + c * 49] = v;
    }
}

extern "C" void kernel_launch(void* const* d_in, const int* in_sizes, int n_in,
                              void* d_out, int out_size) {
    const float* p2   = (const float*)d_in[0];
    const float* p3   = (const float*)d_in[1];
    const float* p4   = (const float*)d_in[2];
    const float* p5   = (const float*)d_in[3];
    const float* rois = (const float*)d_in[4];
    float* out = (float*)d_out;

    int nrois = in_sizes[4] / 4;   // B*R
    if (nrois > MAXROIS) nrois = MAXROIS;

    roi_setup<<<(nrois + 255) / 256, 256>>>(rois, nrois);
    roi_pool<<<nrois, 512>>>(p2, p3, p4, p5, out);
}